// round 2
// baseline (speedup 1.0000x reference)
#include <cuda_runtime.h>

// Problem constants (fixed shapes from reference_code)
#define BB    64
#define WW    300
#define SS    512
#define DD    768
#define LMAXV 4
#define VPT   6          // float4 chunks per lane: (768/4)/32

__device__ int g_first[BB];
__device__ int g_fill[BB];

// Pass 1: per-batch first break index and fill word id (tiny: 64 warps)
__global__ void find_first_kernel(const int* __restrict__ word_index) {
    int b = blockIdx.x;
    int lane = threadIdx.x;
    int best = WW;
    for (int w = lane; w < WW; w += 32) {
        const int* wi = word_index + (b * WW + w) * 3;
        int st = wi[1], en = wi[2];
        if (en < SS && (en - st) <= 0) best = min(best, w);
    }
    #pragma unroll
    for (int o = 16; o; o >>= 1) best = min(best, __shfl_xor_sync(0xffffffffu, best, o));
    if (lane == 0) {
        g_first[b] = best;
        int fw = min(best, WW - 1);
        g_fill[b] = word_index[(b * WW + fw) * 3];
    }
}

// Pass 2: one warp per (b,w) word
__global__ __launch_bounds__(256) void weighted_embed_kernel(
    const float* __restrict__ ernie,
    const float* __restrict__ emb,
    const int*   __restrict__ word_index,
    float*       __restrict__ out)
{
    int gw = blockIdx.x * 8 + (threadIdx.x >> 5);
    if (gw >= BB * WW) return;
    int lane = threadIdx.x & 31;
    int b = gw / WW, w = gw % WW;

    float4* orow = (float4*)(out + (size_t)gw * DD);

    // Fill path: w >= first  ->  out = word_embedding[fill_id]
    if (w >= g_first[b]) {
        const float4* frow = (const float4*)(emb + (size_t)g_fill[b] * DD);
        #pragma unroll
        for (int k = 0; k < VPT; k++) orow[k * 32 + lane] = frow[k * 32 + lane];
        return;
    }

    const int* wi = word_index + gw * 3;
    int wid = wi[0], st = wi[1], en = wi[2];

    // we = word_embedding[wid], kept in registers
    const float4* werow = (const float4*)(emb + (size_t)wid * DD);
    float4 we[VPT];
    #pragma unroll
    for (int k = 0; k < VPT; k++) we[k] = werow[k * 32 + lane];

    // Out-of-range path: out = we
    if (en >= SS) {
        #pragma unroll
        for (int k = 0; k < VPT; k++) orow[k * 32 + lane] = we[k];
        return;
    }

    int span  = en - st;
    int valid = min(max(span, 1), LMAXV);
    const float* eb = ernie + (size_t)b * SS * DD;

    // scores[l] = dot(we, ernie[b, clip(st+l)])
    float score[LMAXV];
    for (int l = 0; l < valid; l++) {
        int pos = min(st + l, SS - 1);
        const float4* crow = (const float4*)(eb + (size_t)pos * DD);
        float acc = 0.f;
        #pragma unroll
        for (int k = 0; k < VPT; k++) {
            float4 c = crow[k * 32 + lane];
            acc += we[k].x * c.x + we[k].y * c.y + we[k].z * c.z + we[k].w * c.w;
        }
        #pragma unroll
        for (int o = 16; o; o >>= 1) acc += __shfl_xor_sync(0xffffffffu, acc, o);
        score[l] = acc;
    }

    // softmax over the valid entries (masked ones are -inf -> excluded)
    float m = score[0];
    for (int l = 1; l < valid; l++) m = fmaxf(m, score[l]);
    float attn[LMAXV];
    float sum = 0.f;
    for (int l = 0; l < valid; l++) { attn[l] = expf(score[l] - m); sum += attn[l]; }
    float inv = 1.f / sum;

    // pooled = sum_l attn[l] * chars[l]   (chars reload hits L1)
    float4 acc4[VPT];
    #pragma unroll
    for (int k = 0; k < VPT; k++) acc4[k] = make_float4(0.f, 0.f, 0.f, 0.f);
    for (int l = 0; l < valid; l++) {
        float a = attn[l] * inv;
        int pos = min(st + l, SS - 1);
        const float4* crow = (const float4*)(eb + (size_t)pos * DD);
        #pragma unroll
        for (int k = 0; k < VPT; k++) {
            float4 c = crow[k * 32 + lane];
            acc4[k].x += a * c.x;
            acc4[k].y += a * c.y;
            acc4[k].z += a * c.z;
            acc4[k].w += a * c.w;
        }
    }
    #pragma unroll
    for (int k = 0; k < VPT; k++) orow[k * 32 + lane] = acc4[k];
}

extern "C" void kernel_launch(void* const* d_in, const int* in_sizes, int n_in,
                              void* d_out, int out_size) {
    const float* ernie = (const float*)d_in[0];
    const float* emb   = (const float*)d_in[1];
    const int*   widx  = (const int*)d_in[2];
    float*       out   = (float*)d_out;

    find_first_kernel<<<BB, 32>>>(widx);
    int total = BB * WW;                      // 19200 warps
    weighted_embed_kernel<<<(total + 7) / 8, 256>>>(ernie, emb, widx, out);
}